// round 11
// baseline (speedup 1.0000x reference)
#include <cuda_runtime.h>
#include <cstdint>

// Problem constants (fixed by the reference: N=64, T=2048, F=256)
#define CBS_N 64
#define CBS_T 2048
#define CBS_F 256
#define CBS_F4 (CBS_F / 4)     // 64 float4 per (n, t) row
#define ROWS_PER_TILE 16        // one tile = 16 rows x 64 f4, 256 threads
#define TILES_PER_N (CBS_T / ROWS_PER_TILE)     // 128
#define TOTAL_TILES (TILES_PER_N * CBS_N)       // 8192

// Persistent single-wave grid: 148 SMs x 8 blocks x 256 thr (regs=30 ->
// 8 blocks/SM co-resident). Each block grid-strides over ~7 tiles. This
// removes the ~7-14 block-wave transitions of the R4-R10 kernels — the
// only untested mechanism behind the invariant 24.4-24.9us plateau
// (DRAM 52%, nothing saturated, insensitive to MLP/cache policy/blocksz).
#define PERSISTENT_BLOCKS (148 * 8)

__device__ __forceinline__ int imax_(int a, int b) { return a > b ? a : b; }
__device__ __forceinline__ int imin_(int a, int b) { return a < b ? a : b; }

__global__ void __launch_bounds__(256)
chunk_by_slices_persist_kernel(const float4* __restrict__ x,
                               const int* __restrict__ slices,
                               const int* __restrict__ lens,
                               float4* __restrict__ out,
                               float* __restrict__ out_lens) {
    const int trow = threadIdx.x >> 4;          // 0..15: row within tile
    const int f0   = threadIdx.x & 15;          // interleaved: f0 + 16k

    for (int tile = blockIdx.x; tile < TOTAL_TILES; tile += PERSISTENT_BLOCKS) {
        const int n  = tile >> 7;               // / TILES_PER_N
        const int tx = tile & (TILES_PER_N - 1);

        // Per-row parameters; uniform across the block -> L1 broadcast.
        const int s = slices[2 * n];
        const int e = slices[2 * n + 1];
        const int chunk_len = imax_(e - s, 0);
        const int left_pad  = (chunk_len == 0) ? 0 : imax_(-s, 0);
        const int start_    = imax_(s, 0);
        const int end_      = imin_(e, lens[n]);
        const int slice_len = imax_(end_ - start_, 0);

        // Fused chunk_lens write: first tile of each n, one thread.
        if (tx == 0 && threadIdx.x == 0) {
            out_lens[n] = (float)chunk_len;
        }

        const int t = tx * ROWS_PER_TILE + trow;

        const bool valid = (t >= left_pad) && (t < left_pad + slice_len);

        int src = start_ + t - left_pad;
        src = imin_(imax_(src, 0), CBS_T - 1);

        float4 v0, v1, v2, v3;
        if (valid) {
            const float4* xr = &x[(n * CBS_T + src) * CBS_F4 + f0];
            v0 = __ldg(xr + 0);
            v1 = __ldg(xr + 16);
            v2 = __ldg(xr + 32);
            v3 = __ldg(xr + 48);
        } else {
            v0 = v1 = v2 = v3 = make_float4(0.f, 0.f, 0.f, 0.f);
        }

        float4* op = &out[(n * CBS_T + t) * CBS_F4 + f0];
        __stcs(op + 0,  v0);    // output never re-read: evict-first
        __stcs(op + 16, v1);
        __stcs(op + 32, v2);
        __stcs(op + 48, v3);
    }
}

extern "C" void kernel_launch(void* const* d_in, const int* in_sizes, int n_in,
                              void* d_out, int out_size) {
    const float4* x      = (const float4*)d_in[0];
    const int*    slices = (const int*)d_in[1];
    const int*    lens   = (const int*)d_in[2];
    float4*       out    = (float4*)d_out;

    const long long chunks_elems = (long long)CBS_N * CBS_T * CBS_F;
    float* out_lens = ((float*)d_out) + chunks_elems;

    chunk_by_slices_persist_kernel<<<PERSISTENT_BLOCKS, 256>>>(
        x, slices, lens, out, out_lens);
}